// round 6
// baseline (speedup 1.0000x reference)
#include <cuda_runtime.h>
#include <cuda_bf16.h>
#include <cstdint>

#define MAX_N 100000
#define MAX_E 1700000
#define FDIM  128
#define CHUNK 1024

// Scratch (allocation-free: __device__ globals)
__device__ float g_H[(size_t)MAX_N * FDIM];
__device__ float g_O[(size_t)MAX_N * FDIM];
__device__ float g_dinv[MAX_N];
__device__ float g_dinv2[MAX_N];
__device__ int   g_cnt[MAX_N];
__device__ int   g_pos[MAX_N];
__device__ int   g_rowStart[MAX_N];
__device__ int   g_wcur[MAX_N];
__device__ int   g_chunkSum[256];
__device__ int   g_es[MAX_E];
__device__ float g_en[MAX_E];

// ---------------------------------------------------------------------------
__global__ void k_zero_cnt(int n) {
    int i = blockIdx.x * blockDim.x + threadIdx.x;
    if (i < n) g_cnt[i] = 0;
}

__global__ void k_hist(const int* __restrict__ ei, int E) {
    int e = blockIdx.x * blockDim.x + threadIdx.x;
    if (e < E) atomicAdd(&g_cnt[ei[E + e]], 1);
}

__global__ __launch_bounds__(256) void k_scan1(int n) {
    __shared__ int sh[256];
    int t = threadIdx.x;
    int base = blockIdx.x * CHUNK + t * 4;
    int v0 = (base + 0 < n) ? g_cnt[base + 0] : 0;
    int v1 = (base + 1 < n) ? g_cnt[base + 1] : 0;
    int v2 = (base + 2 < n) ? g_cnt[base + 2] : 0;
    int v3 = (base + 3 < n) ? g_cnt[base + 3] : 0;
    int tsum = v0 + v1 + v2 + v3;
    sh[t] = tsum;
    __syncthreads();
    for (int off = 1; off < 256; off <<= 1) {
        int x = (t >= off) ? sh[t - off] : 0;
        __syncthreads();
        sh[t] += x;
        __syncthreads();
    }
    int texcl = sh[t] - tsum;
    if (base + 0 < n) g_pos[base + 0] = texcl;
    if (base + 1 < n) g_pos[base + 1] = texcl + v0;
    if (base + 2 < n) g_pos[base + 2] = texcl + v0 + v1;
    if (base + 3 < n) g_pos[base + 3] = texcl + v0 + v1 + v2;
    if (t == 255) g_chunkSum[blockIdx.x] = sh[255];
}

__global__ __launch_bounds__(256) void k_scan2(int nChunks) {
    __shared__ int sh[256];
    int t = threadIdx.x;
    int v = (t < nChunks) ? g_chunkSum[t] : 0;
    sh[t] = v;
    __syncthreads();
    for (int off = 1; off < 256; off <<= 1) {
        int x = (t >= off) ? sh[t - off] : 0;
        __syncthreads();
        sh[t] += x;
        __syncthreads();
    }
    if (t < nChunks) g_chunkSum[t] = sh[t] - v;
}

__global__ void k_scan3(int n) {
    int i = blockIdx.x * blockDim.x + threadIdx.x;
    if (i < n) {
        int rs = g_pos[i] + g_chunkSum[i / CHUNK];
        g_rowStart[i] = rs;
        g_wcur[i]     = rs;
        float di = rsqrtf((float)g_cnt[i] + 1.0f);
        g_dinv[i]  = di;
        g_dinv2[i] = di * di;
    }
}

__global__ void k_build(const int* __restrict__ ei, int E) {
    int e = blockIdx.x * blockDim.x + threadIdx.x;
    if (e < E) {
        int s = ei[e];
        int d = ei[E + e];
        int p = atomicAdd(&g_wcur[d], 1);
        g_es[p] = s;
        g_en[p] = g_dinv[s] * g_dinv[d];
    }
}

// ---------------------------------------------------------------------------
// MMA helpers
__device__ __forceinline__ void ldsm4(uint32_t* r, uint32_t addr) {
    asm volatile("ldmatrix.sync.aligned.m8n8.x4.shared.b16 {%0,%1,%2,%3}, [%4];"
        : "=r"(r[0]), "=r"(r[1]), "=r"(r[2]), "=r"(r[3]) : "r"(addr));
}
__device__ __forceinline__ void mma16816(float* c, const uint32_t* a, const uint32_t* b) {
    asm volatile(
        "mma.sync.aligned.m16n8k16.row.col.f32.bf16.bf16.f32 "
        "{%0,%1,%2,%3}, {%4,%5,%6,%7}, {%8,%9}, {%0,%1,%2,%3};"
        : "+f"(c[0]), "+f"(c[1]), "+f"(c[2]), "+f"(c[3])
        : "r"(a[0]), "r"(a[1]), "r"(a[2]), "r"(a[3]), "r"(b[0]), "r"(b[1]));
}
__device__ __forceinline__ void split_bf16(float x, __nv_bfloat16& hi, __nv_bfloat16& lo) {
    hi = __float2bfloat16(x);
    lo = __float2bfloat16(x - __bfloat162float(hi));
}

// ---------------------------------------------------------------------------
// Tensor-core SGEMM via bf16 3-term split: h = X @ W  (fp32 in/out).
// Block tile 128x128, 8 warps (4m x 2n), warp tile 32x64 (m16n8k16 frags).
// K in chunks of 32; X,W converted to (hi,lo) bf16 in smem each chunk.
// W stored TRANSPOSED in smem (b[n][k]) so B frags load with plain ldmatrix.
#define APAD 40   // row stride in bf16 elems (32 + 8 pad)
__global__ __launch_bounds__(256) void k_gemm(
    const float* __restrict__ X, const float* __restrict__ W, int N)
{
    __shared__ __nv_bfloat16 a_hi[128][APAD];
    __shared__ __nv_bfloat16 a_lo[128][APAD];
    __shared__ __nv_bfloat16 b_hi[128][APAD];   // [n][k]
    __shared__ __nv_bfloat16 b_lo[128][APAD];

    int t    = threadIdx.x;
    int wid  = t >> 5;
    int lane = t & 31;
    int warp_m = wid & 3;       // 0..3 -> rows 32*warp_m
    int warp_n = wid >> 2;      // 0..1 -> cols 64*warp_n
    int rowbase = blockIdx.x * 128;

    float acc[2][8][4];
#pragma unroll
    for (int i = 0; i < 2; i++)
#pragma unroll
        for (int j = 0; j < 8; j++)
#pragma unroll
            for (int q = 0; q < 4; q++) acc[i][j][q] = 0.f;

    for (int kc = 0; kc < 128; kc += 32) {
        // --- Fill A (hi/lo): 128 rows x 32 k; 1024 float4 loads, 4/thread ---
#pragma unroll
        for (int i = 0; i < 4; i++) {
            int idx = t + i * 256;
            int row = idx >> 3;
            int k4  = (idx & 7) * 4;
            int grow = rowbase + row;
            float4 v = (grow < N)
                ? *(const float4*)&X[(size_t)grow * FDIM + kc + k4]
                : make_float4(0.f, 0.f, 0.f, 0.f);
            float xs4[4] = {v.x, v.y, v.z, v.w};
#pragma unroll
            for (int j = 0; j < 4; j++) {
                __nv_bfloat16 h, l;
                split_bf16(xs4[j], h, l);
                a_hi[row][k4 + j] = h;
                a_lo[row][k4 + j] = l;
            }
        }
        // --- Fill B transposed (hi/lo): W[kc+kk][n] -> b[n][kk] ---
#pragma unroll
        for (int i = 0; i < 4; i++) {
            int idx = t + i * 256;
            int kk = idx >> 5;             // 0..31
            int n4 = (idx & 31) * 4;       // 0..124
            float4 v = *(const float4*)&W[(size_t)(kc + kk) * FDIM + n4];
            float ws4[4] = {v.x, v.y, v.z, v.w};
#pragma unroll
            for (int j = 0; j < 4; j++) {
                __nv_bfloat16 h, l;
                split_bf16(ws4[j], h, l);
                b_hi[n4 + j][kk] = h;
                b_lo[n4 + j][kk] = l;
            }
        }
        __syncthreads();

        // --- 2 k16 steps per chunk ---
#pragma unroll
        for (int s = 0; s < 2; s++) {
            int kb = s * 16;
            // A frags: row = m_base + (lane&15), k = kb + 8*(lane>>4)
            uint32_t ah[2][4], al[2][4];
#pragma unroll
            for (int mi = 0; mi < 2; mi++) {
                int mrow = warp_m * 32 + mi * 16 + (lane & 15);
                int kcol = kb + ((lane >> 4) << 3);
                ldsm4(ah[mi], (uint32_t)__cvta_generic_to_shared(&a_hi[mrow][kcol]));
                ldsm4(al[mi], (uint32_t)__cvta_generic_to_shared(&a_lo[mrow][kcol]));
            }
            // B frags: per n16 block: n = n_base + 8*(lane>>4) + (lane&7),
            //          k = kb + 8*((lane>>3)&1)
            uint32_t bh[8][2], bl[8][2];
#pragma unroll
            for (int nb = 0; nb < 4; nb++) {
                int nrow = warp_n * 64 + nb * 16 + ((lane >> 4) << 3) + (lane & 7);
                int kcol = kb + (((lane >> 3) & 1) << 3);
                uint32_t r[4];
                ldsm4(r, (uint32_t)__cvta_generic_to_shared(&b_hi[nrow][kcol]));
                bh[nb*2][0] = r[0]; bh[nb*2][1] = r[1];
                bh[nb*2+1][0] = r[2]; bh[nb*2+1][1] = r[3];
                ldsm4(r, (uint32_t)__cvta_generic_to_shared(&b_lo[nrow][kcol]));
                bl[nb*2][0] = r[0]; bl[nb*2][1] = r[1];
                bl[nb*2+1][0] = r[2]; bl[nb*2+1][1] = r[3];
            }
            // MMAs: hi*hi + hi*lo + lo*hi
#pragma unroll
            for (int mi = 0; mi < 2; mi++)
#pragma unroll
                for (int nj = 0; nj < 8; nj++) {
                    mma16816(acc[mi][nj], ah[mi], bh[nj]);
                    mma16816(acc[mi][nj], ah[mi], bl[nj]);
                    mma16816(acc[mi][nj], al[mi], bh[nj]);
                }
        }
        __syncthreads();
    }

    // --- Store C: c0,c1 -> (row = base + lane/4, col = nj*8 + 2*(lane%4)),
    //              c2,c3 -> row + 8 ---
#pragma unroll
    for (int mi = 0; mi < 2; mi++) {
        int r0 = rowbase + warp_m * 32 + mi * 16 + (lane >> 2);
        int r1 = r0 + 8;
#pragma unroll
        for (int nj = 0; nj < 8; nj++) {
            int col = warp_n * 64 + nj * 8 + 2 * (lane & 3);
            if (r0 < N)
                *(float2*)&g_H[(size_t)r0 * FDIM + col] =
                    make_float2(acc[mi][nj][0], acc[mi][nj][1]);
            if (r1 < N)
                *(float2*)&g_H[(size_t)r1 * FDIM + col] =
                    make_float2(acc[mi][nj][2], acc[mi][nj][3]);
        }
    }
}

// ---------------------------------------------------------------------------
// Pull-based aggregation + self-loop + bias + relu, fused.
__global__ __launch_bounds__(256) void k_gather(
    const float* __restrict__ h, const float* __restrict__ b,
    float* __restrict__ out, int N, int relu)
{
    int warp = (blockIdx.x * 256 + threadIdx.x) >> 5;
    int lane = threadIdx.x & 31;
    if (warp >= N) return;

    int row   = warp;
    int start = g_rowStart[row];
    int cnt   = g_cnt[row];

    float d2 = g_dinv2[row];
    float4 acc = __ldg((const float4*)(h + (size_t)row * FDIM) + lane);
    acc.x *= d2; acc.y *= d2; acc.z *= d2; acc.w *= d2;

    for (int e0 = 0; e0 < cnt; e0 += 32) {
        int mye = e0 + lane;
        int s = 0; float nm = 0.f;
        if (mye < cnt) {
            s  = __ldg(&g_es[start + mye]);
            nm = __ldg(&g_en[start + mye]);
        }
        int m = min(32, cnt - e0);
#pragma unroll 4
        for (int j = 0; j < m; j++) {
            int   sj = __shfl_sync(0xffffffffu, s,  j);
            float nj = __shfl_sync(0xffffffffu, nm, j);
            float4 v = __ldg((const float4*)(h + (size_t)sj * FDIM) + lane);
            acc.x = fmaf(v.x, nj, acc.x);
            acc.y = fmaf(v.y, nj, acc.y);
            acc.z = fmaf(v.z, nj, acc.z);
            acc.w = fmaf(v.w, nj, acc.w);
        }
    }

    float4 bb = __ldg((const float4*)b + lane);
    acc.x += bb.x; acc.y += bb.y; acc.z += bb.z; acc.w += bb.w;
    if (relu) {
        acc.x = fmaxf(acc.x, 0.f); acc.y = fmaxf(acc.y, 0.f);
        acc.z = fmaxf(acc.z, 0.f); acc.w = fmaxf(acc.w, 0.f);
    }
    ((float4*)(out + (size_t)row * FDIM))[lane] = acc;
}

// ---------------------------------------------------------------------------
extern "C" void kernel_launch(void* const* d_in, const int* in_sizes, int n_in,
                              void* d_out, int out_size)
{
    const float* x  = (const float*)d_in[0];
    const int*   ei = (const int*)d_in[1];   // int32 (JAX x64 disabled)
    const float* W1 = (const float*)d_in[2];
    const float* b1 = (const float*)d_in[3];
    const float* W2 = (const float*)d_in[4];
    const float* b2 = (const float*)d_in[5];
    const float* W3 = (const float*)d_in[6];
    const float* b3 = (const float*)d_in[7];
    float* out = (float*)d_out;

    int N = in_sizes[0] / FDIM;
    int E = in_sizes[1] / 2;

    float *H, *O;
    cudaGetSymbolAddress((void**)&H, g_H);
    cudaGetSymbolAddress((void**)&O, g_O);

    int nThr = 256;
    int nBlkN    = (N + nThr - 1) / nThr;
    int nBlkE    = (E + nThr - 1) / nThr;
    int nBlkGemm = (N + 127) / 128;
    int nChunks  = (N + CHUNK - 1) / CHUNK;
    long long gthreads = (long long)N * 32;
    int nBlkGather = (int)((gthreads + nThr - 1) / nThr);

    // --- CSR build (once per launch) ---
    k_zero_cnt<<<nBlkN, nThr>>>(N);
    k_hist<<<nBlkE, nThr>>>(ei, E);
    k_scan1<<<nChunks, nThr>>>(N);
    k_scan2<<<1, nThr>>>(nChunks);
    k_scan3<<<nBlkN, nThr>>>(N);
    k_build<<<nBlkE, nThr>>>(ei, E);

    // Layer 1: x -> H -> O (relu)
    k_gemm<<<nBlkGemm, nThr>>>(x, W1, N);
    k_gather<<<nBlkGather, nThr>>>(H, b1, O, N, 1);

    // Layer 2: O -> H -> O (relu)
    k_gemm<<<nBlkGemm, nThr>>>(O, W2, N);
    k_gather<<<nBlkGather, nThr>>>(H, b2, O, N, 1);

    // Layer 3: O -> H -> out (no relu)
    k_gemm<<<nBlkGemm, nThr>>>(O, W3, N);
    k_gather<<<nBlkGather, nThr>>>(H, b3, out, N, 0);
}

// round 7
// speedup vs baseline: 1.4690x; 1.4690x over previous
#include <cuda_runtime.h>
#include <cuda_bf16.h>
#include <cstdint>

#define MAX_N 100000
#define MAX_E 1700000
#define FDIM  128
#define CHUNK 1024

// Scratch (allocation-free: __device__ globals)
__device__ float g_H[(size_t)MAX_N * FDIM];
__device__ __nv_bfloat16 g_xhi[(size_t)MAX_N * FDIM];
__device__ __nv_bfloat16 g_xlo[(size_t)MAX_N * FDIM];
__device__ __nv_bfloat16 g_wthi[3 * FDIM * FDIM];   // transposed [n][k]
__device__ __nv_bfloat16 g_wtlo[3 * FDIM * FDIM];
__device__ float g_dinv[MAX_N];
__device__ float g_dinv2[MAX_N];
__device__ int   g_cnt[MAX_N];
__device__ int   g_pos[MAX_N];
__device__ int   g_rowStart[MAX_N];
__device__ int   g_wcur[MAX_N];
__device__ int   g_chunkSum[256];
__device__ int   g_es[MAX_E];
__device__ float g_en[MAX_E];

__device__ __forceinline__ void split_bf16(float x, __nv_bfloat16& hi, __nv_bfloat16& lo) {
    hi = __float2bfloat16(x);
    lo = __float2bfloat16(x - __bfloat162float(hi));
}

// ---------------------------------------------------------------------------
__global__ void k_zero_cnt(int n) {
    int i = blockIdx.x * blockDim.x + threadIdx.x;
    if (i < n) g_cnt[i] = 0;
}

__global__ void k_hist(const int* __restrict__ ei, int E) {
    int e = blockIdx.x * blockDim.x + threadIdx.x;
    if (e < E) atomicAdd(&g_cnt[ei[E + e]], 1);
}

__global__ __launch_bounds__(256) void k_scan1(int n) {
    __shared__ int sh[256];
    int t = threadIdx.x;
    int base = blockIdx.x * CHUNK + t * 4;
    int v0 = (base + 0 < n) ? g_cnt[base + 0] : 0;
    int v1 = (base + 1 < n) ? g_cnt[base + 1] : 0;
    int v2 = (base + 2 < n) ? g_cnt[base + 2] : 0;
    int v3 = (base + 3 < n) ? g_cnt[base + 3] : 0;
    int tsum = v0 + v1 + v2 + v3;
    sh[t] = tsum;
    __syncthreads();
    for (int off = 1; off < 256; off <<= 1) {
        int x = (t >= off) ? sh[t - off] : 0;
        __syncthreads();
        sh[t] += x;
        __syncthreads();
    }
    int texcl = sh[t] - tsum;
    if (base + 0 < n) g_pos[base + 0] = texcl;
    if (base + 1 < n) g_pos[base + 1] = texcl + v0;
    if (base + 2 < n) g_pos[base + 2] = texcl + v0 + v1;
    if (base + 3 < n) g_pos[base + 3] = texcl + v0 + v1 + v2;
    if (t == 255) g_chunkSum[blockIdx.x] = sh[255];
}

__global__ __launch_bounds__(256) void k_scan2(int nChunks) {
    __shared__ int sh[256];
    int t = threadIdx.x;
    int v = (t < nChunks) ? g_chunkSum[t] : 0;
    sh[t] = v;
    __syncthreads();
    for (int off = 1; off < 256; off <<= 1) {
        int x = (t >= off) ? sh[t - off] : 0;
        __syncthreads();
        sh[t] += x;
        __syncthreads();
    }
    if (t < nChunks) g_chunkSum[t] = sh[t] - v;
}

__global__ void k_scan3(int n) {
    int i = blockIdx.x * blockDim.x + threadIdx.x;
    if (i < n) {
        int rs = g_pos[i] + g_chunkSum[i / CHUNK];
        g_rowStart[i] = rs;
        g_wcur[i]     = rs;
        float di = rsqrtf((float)g_cnt[i] + 1.0f);
        g_dinv[i]  = di;
        g_dinv2[i] = di * di;
    }
}

__global__ void k_build(const int* __restrict__ ei, int E) {
    int e = blockIdx.x * blockDim.x + threadIdx.x;
    if (e < E) {
        int s = ei[e];
        int d = ei[E + e];
        int p = atomicAdd(&g_wcur[d], 1);
        g_es[p] = s;
        g_en[p] = g_dinv[s] * g_dinv[d];
    }
}

// ---------------------------------------------------------------------------
// Convert x (fp32) -> xhi/xlo (bf16). 8 floats per thread.
__global__ void k_convertX(const float* __restrict__ x, long long n8) {
    long long i = (long long)blockIdx.x * blockDim.x + threadIdx.x;
    if (i >= n8) return;
    const float4* xp = (const float4*)x + i * 2;
    float4 v0 = __ldg(xp), v1 = __ldg(xp + 1);
    float f[8] = {v0.x, v0.y, v0.z, v0.w, v1.x, v1.y, v1.z, v1.w};
    __nv_bfloat16 hi[8], lo[8];
#pragma unroll
    for (int j = 0; j < 8; j++) split_bf16(f[j], hi[j], lo[j]);
    *(uint4*)&g_xhi[i * 8] = *(uint4*)hi;
    *(uint4*)&g_xlo[i * 8] = *(uint4*)lo;
}

// Convert W (fp32 [k][n]) -> transposed wt_hi/wt_lo (bf16 [n][k]).
__global__ void k_convertW(const float* __restrict__ W, int slot) {
    int idx = blockIdx.x * blockDim.x + threadIdx.x;  // 16384
    int n = idx >> 7, k = idx & 127;
    __nv_bfloat16 hi, lo;
    split_bf16(__ldg(&W[k * FDIM + n]), hi, lo);
    g_wthi[slot * FDIM * FDIM + idx] = hi;
    g_wtlo[slot * FDIM * FDIM + idx] = lo;
}

// ---------------------------------------------------------------------------
// MMA helpers
__device__ __forceinline__ void ldsm4(uint32_t* r, uint32_t addr) {
    asm volatile("ldmatrix.sync.aligned.m8n8.x4.shared.b16 {%0,%1,%2,%3}, [%4];"
        : "=r"(r[0]), "=r"(r[1]), "=r"(r[2]), "=r"(r[3]) : "r"(addr));
}
__device__ __forceinline__ void mma16816(float* c, const uint32_t* a, const uint32_t* b) {
    asm volatile(
        "mma.sync.aligned.m16n8k16.row.col.f32.bf16.bf16.f32 "
        "{%0,%1,%2,%3}, {%4,%5,%6,%7}, {%8,%9}, {%0,%1,%2,%3};"
        : "+f"(c[0]), "+f"(c[1]), "+f"(c[2]), "+f"(c[3])
        : "r"(a[0]), "r"(a[1]), "r"(a[2]), "r"(a[3]), "r"(b[0]), "r"(b[1]));
}

// ---------------------------------------------------------------------------
// Tensor-core GEMM, inputs pre-split bf16: h = (Xhi+Xlo) @ (Whi+Wlo),
// 3-term (drop lo*lo). Block tile 128x128, 8 warps (4m x 2n).
// Fill path: pure uint4 LDG -> STS.128, no conversion.
#define APAD 40
__global__ __launch_bounds__(256) void k_gemm(
    const __nv_bfloat16* __restrict__ Xhi, const __nv_bfloat16* __restrict__ Xlo,
    const __nv_bfloat16* __restrict__ Wthi, const __nv_bfloat16* __restrict__ Wtlo,
    int N)
{
    __shared__ __nv_bfloat16 a_hi[128][APAD];
    __shared__ __nv_bfloat16 a_lo[128][APAD];
    __shared__ __nv_bfloat16 b_hi[128][APAD];   // [n][k]
    __shared__ __nv_bfloat16 b_lo[128][APAD];

    int t    = threadIdx.x;
    int wid  = t >> 5;
    int lane = t & 31;
    int warp_m = wid & 3;
    int warp_n = wid >> 2;
    int rowbase = blockIdx.x * 128;

    float acc[2][8][4];
#pragma unroll
    for (int i = 0; i < 2; i++)
#pragma unroll
        for (int j = 0; j < 8; j++)
#pragma unroll
            for (int q = 0; q < 4; q++) acc[i][j][q] = 0.f;

    for (int kc = 0; kc < 128; kc += 32) {
        // A fill: 128 rows x 32 k; 512 uint4 per array, 2 per thread.
#pragma unroll
        for (int i = 0; i < 2; i++) {
            int idx = t + i * 256;
            int row = idx >> 2;
            int k8  = (idx & 3) * 8;
            int grow = rowbase + row;
            uint4 vh, vl;
            if (grow < N) {
                size_t off = (size_t)grow * FDIM + kc + k8;
                vh = *(const uint4*)&Xhi[off];
                vl = *(const uint4*)&Xlo[off];
            } else {
                vh = make_uint4(0, 0, 0, 0);
                vl = make_uint4(0, 0, 0, 0);
            }
            *(uint4*)&a_hi[row][k8] = vh;
            *(uint4*)&a_lo[row][k8] = vl;
        }
        // B fill from transposed W: [n][k]
#pragma unroll
        for (int i = 0; i < 2; i++) {
            int idx = t + i * 256;
            int nrow = idx >> 2;
            int k8   = (idx & 3) * 8;
            size_t off = (size_t)nrow * FDIM + kc + k8;
            *(uint4*)&b_hi[nrow][k8] = *(const uint4*)&Wthi[off];
            *(uint4*)&b_lo[nrow][k8] = *(const uint4*)&Wtlo[off];
        }
        __syncthreads();

#pragma unroll
        for (int s = 0; s < 2; s++) {
            int kb = s * 16;
            uint32_t ah[2][4], al[2][4];
#pragma unroll
            for (int mi = 0; mi < 2; mi++) {
                int mrow = warp_m * 32 + mi * 16 + (lane & 15);
                int kcol = kb + ((lane >> 4) << 3);
                ldsm4(ah[mi], (uint32_t)__cvta_generic_to_shared(&a_hi[mrow][kcol]));
                ldsm4(al[mi], (uint32_t)__cvta_generic_to_shared(&a_lo[mrow][kcol]));
            }
            uint32_t bh[8][2], bl[8][2];
#pragma unroll
            for (int nb = 0; nb < 4; nb++) {
                int nrow = warp_n * 64 + nb * 16 + ((lane >> 4) << 3) + (lane & 7);
                int kcol = kb + (((lane >> 3) & 1) << 3);
                uint32_t r[4];
                ldsm4(r, (uint32_t)__cvta_generic_to_shared(&b_hi[nrow][kcol]));
                bh[nb*2][0] = r[0]; bh[nb*2][1] = r[1];
                bh[nb*2+1][0] = r[2]; bh[nb*2+1][1] = r[3];
                ldsm4(r, (uint32_t)__cvta_generic_to_shared(&b_lo[nrow][kcol]));
                bl[nb*2][0] = r[0]; bl[nb*2][1] = r[1];
                bl[nb*2+1][0] = r[2]; bl[nb*2+1][1] = r[3];
            }
#pragma unroll
            for (int mi = 0; mi < 2; mi++)
#pragma unroll
                for (int nj = 0; nj < 8; nj++) {
                    mma16816(acc[mi][nj], ah[mi], bh[nj]);
                    mma16816(acc[mi][nj], ah[mi], bl[nj]);
                    mma16816(acc[mi][nj], al[mi], bh[nj]);
                }
        }
        __syncthreads();
    }

#pragma unroll
    for (int mi = 0; mi < 2; mi++) {
        int r0 = rowbase + warp_m * 32 + mi * 16 + (lane >> 2);
        int r1 = r0 + 8;
#pragma unroll
        for (int nj = 0; nj < 8; nj++) {
            int col = warp_n * 64 + nj * 8 + 2 * (lane & 3);
            if (r0 < N)
                *(float2*)&g_H[(size_t)r0 * FDIM + col] =
                    make_float2(acc[mi][nj][0], acc[mi][nj][1]);
            if (r1 < N)
                *(float2*)&g_H[(size_t)r1 * FDIM + col] =
                    make_float2(acc[mi][nj][2], acc[mi][nj][3]);
        }
    }
}

// ---------------------------------------------------------------------------
// Pull-based aggregation + self-loop + bias + relu, fused.
// mode 0: write bf16 hi/lo split into g_xhi/g_xlo (feeds next GEMM), relu.
// mode 1: write fp32 to ofp (final layer), no relu.
__global__ __launch_bounds__(256) void k_gather(
    const float* __restrict__ h, const float* __restrict__ b,
    float* __restrict__ ofp, int N, int mode)
{
    int warp = (blockIdx.x * 256 + threadIdx.x) >> 5;
    int lane = threadIdx.x & 31;
    if (warp >= N) return;

    int row   = warp;
    int start = g_rowStart[row];
    int cnt   = g_cnt[row];

    float d2 = g_dinv2[row];
    float4 acc = __ldg((const float4*)(h + (size_t)row * FDIM) + lane);
    acc.x *= d2; acc.y *= d2; acc.z *= d2; acc.w *= d2;

    for (int e0 = 0; e0 < cnt; e0 += 32) {
        int mye = e0 + lane;
        int s = 0; float nm = 0.f;
        if (mye < cnt) {
            s  = __ldg(&g_es[start + mye]);
            nm = __ldg(&g_en[start + mye]);
        }
        int m = min(32, cnt - e0);
#pragma unroll 4
        for (int j = 0; j < m; j++) {
            int   sj = __shfl_sync(0xffffffffu, s,  j);
            float nj = __shfl_sync(0xffffffffu, nm, j);
            float4 v = __ldg((const float4*)(h + (size_t)sj * FDIM) + lane);
            acc.x = fmaf(v.x, nj, acc.x);
            acc.y = fmaf(v.y, nj, acc.y);
            acc.z = fmaf(v.z, nj, acc.z);
            acc.w = fmaf(v.w, nj, acc.w);
        }
    }

    float4 bb = __ldg((const float4*)b + lane);
    acc.x += bb.x; acc.y += bb.y; acc.z += bb.z; acc.w += bb.w;

    if (mode == 0) {
        // relu + bf16 hi/lo split, feeds next layer's GEMM
        float f[4];
        f[0] = fmaxf(acc.x, 0.f); f[1] = fmaxf(acc.y, 0.f);
        f[2] = fmaxf(acc.z, 0.f); f[3] = fmaxf(acc.w, 0.f);
        __nv_bfloat16 hi[4], lo[4];
#pragma unroll
        for (int j = 0; j < 4; j++) split_bf16(f[j], hi[j], lo[j]);
        size_t off = (size_t)row * FDIM + lane * 4;
        *(uint2*)&g_xhi[off] = *(uint2*)hi;
        *(uint2*)&g_xlo[off] = *(uint2*)lo;
    } else {
        ((float4*)(ofp + (size_t)row * FDIM))[lane] = acc;
    }
}

// ---------------------------------------------------------------------------
extern "C" void kernel_launch(void* const* d_in, const int* in_sizes, int n_in,
                              void* d_out, int out_size)
{
    const float* x  = (const float*)d_in[0];
    const int*   ei = (const int*)d_in[1];   // int32 (JAX x64 disabled)
    const float* W1 = (const float*)d_in[2];
    const float* b1 = (const float*)d_in[3];
    const float* W2 = (const float*)d_in[4];
    const float* b2 = (const float*)d_in[5];
    const float* W3 = (const float*)d_in[6];
    const float* b3 = (const float*)d_in[7];
    float* out = (float*)d_out;

    int N = in_sizes[0] / FDIM;
    int E = in_sizes[1] / 2;

    float* H;
    cudaGetSymbolAddress((void**)&H, g_H);
    __nv_bfloat16 *XHI, *XLO, *WTHI, *WTLO;
    cudaGetSymbolAddress((void**)&XHI,  g_xhi);
    cudaGetSymbolAddress((void**)&XLO,  g_xlo);
    cudaGetSymbolAddress((void**)&WTHI, g_wthi);
    cudaGetSymbolAddress((void**)&WTLO, g_wtlo);

    int nThr = 256;
    int nBlkN    = (N + nThr - 1) / nThr;
    int nBlkE    = (E + nThr - 1) / nThr;
    int nBlkGemm = (N + 127) / 128;
    int nChunks  = (N + CHUNK - 1) / CHUNK;
    long long gthreads = (long long)N * 32;
    int nBlkGather = (int)((gthreads + nThr - 1) / nThr);
    long long n8 = (long long)N * FDIM / 8;
    int nBlkConv = (int)((n8 + nThr - 1) / nThr);

    // --- one-time per launch: conversions + CSR build ---
    k_convertX<<<nBlkConv, nThr>>>(x, n8);
    k_convertW<<<64, nThr>>>(W1, 0);
    k_convertW<<<64, nThr>>>(W2, 1);
    k_convertW<<<64, nThr>>>(W3, 2);

    k_zero_cnt<<<nBlkN, nThr>>>(N);
    k_hist<<<nBlkE, nThr>>>(ei, E);
    k_scan1<<<nChunks, nThr>>>(N);
    k_scan2<<<1, nThr>>>(nChunks);
    k_scan3<<<nBlkN, nThr>>>(N);
    k_build<<<nBlkE, nThr>>>(ei, E);

    const int WSZ = FDIM * FDIM;
    // Layer 1: xhi/xlo -> H -> xhi/xlo (relu+split)
    k_gemm<<<nBlkGemm, nThr>>>(XHI, XLO, WTHI, WTLO, N);
    k_gather<<<nBlkGather, nThr>>>(H, b1, nullptr, N, 0);

    // Layer 2
    k_gemm<<<nBlkGemm, nThr>>>(XHI, XLO, WTHI + WSZ, WTLO + WSZ, N);
    k_gather<<<nBlkGather, nThr>>>(H, b2, nullptr, N, 0);

    // Layer 3: fp32 out, no relu
    k_gemm<<<nBlkGemm, nThr>>>(XHI, XLO, WTHI + 2*WSZ, WTLO + 2*WSZ, N);
    k_gather<<<nBlkGather, nThr>>>(H, b3, out, N, 1);
}